// round 14
// baseline (speedup 1.0000x reference)
#include <cuda_runtime.h>
#include <cuda_bf16.h>
#include <cstdint>

#define B_    64
#define T_    512
#define H_    1024
#define D_    512
#define GB_   4     // batch groups
#define CPG_  32    // CTAs (chunks) per group
#define BPG_  16    // batches per group
#define CHPC_ 32    // channels per CTA
#define NCTA_ (GB_*CPG_)
#define NTHR_ 512
#define SLOTS_ 4

#define PSB_  2064              // padded plane row stride in BYTES (1032 bf16)
#define WH_OFF 0
#define WL_OFF (32 * PSB_)               // 66048
#define SH_OFF (2 * 32 * PSB_)           // 132096
#define SL_OFF (SH_OFF + 16 * PSB_)      // 165120
#define RED_OFF (SL_OFF + 16 * PSB_)     // 198144 (dedicated, no overlay)
#define REDLN_OFF (RED_OFF + 4*16*34*4)  // 206848  (stride 34 floats = EVEN -> 8B aligned)
#define BC_OFF (REDLN_OFF + 512)         // 207360
#define SMEM_BYTES (BC_OFF + 160)

// u_gemm_mma SMEM layout: 4 planes of 128 rows x 144B + bias
#define UPAD_ 144
#define UA_H 0
#define UA_L (128 * UPAD_)
#define UB_H (2 * 128 * UPAD_)
#define UB_L (3 * 128 * UPAD_)
#define UBIAS (4 * 128 * UPAD_)
#define USMEM_BYTES (UBIAS + 512 + 32)

// scratch (static __device__ arrays: zero at module load, allocation-free)
__device__ float    g_u[(size_t)T_ * B_ * H_];       // u drive [t][b][h]
__device__ uint32_t g_stp[SLOTS_][B_][H_];           // packed state (hi<<16|lo bf16)
__device__ int      g_flag[T_ + 1][GB_][CPG_];       // monotonic chunk-ready counters
__device__ __nv_bfloat16 g_xh[(size_t)B_ * T_ * D_]; // x hi plane
__device__ __nv_bfloat16 g_xl[(size_t)B_ * T_ * D_]; // x lo plane
__device__ __nv_bfloat16 g_wh[(size_t)H_ * D_];      // W_in hi plane
__device__ __nv_bfloat16 g_wl[(size_t)H_ * D_];      // W_in lo plane

// ---- bf16 split helpers ----
__device__ __forceinline__ uint32_t pack_bf(float s) {
    __nv_bfloat16 h = __float2bfloat16(s);
    float hf = __bfloat162float(h);
    __nv_bfloat16 lo = __float2bfloat16(s - hf);
    return ((uint32_t)__bfloat16_as_ushort(h) << 16) |
           (uint32_t)__bfloat16_as_ushort(lo);
}
__device__ __forceinline__ float unpack_f(uint32_t p) {
    __nv_bfloat16 h = __ushort_as_bfloat16((unsigned short)(p >> 16));
    __nv_bfloat16 l = __ushort_as_bfloat16((unsigned short)(p & 0xffff));
    return __bfloat162float(h) + __bfloat162float(l);
}

// relaxed gpu-scope flag load (poll); pair with fence.acq_rel before data reads
__device__ __forceinline__ int ld_flag(const int* p) {
    int v;
    asm volatile("ld.relaxed.gpu.global.b32 %0, [%1];" : "=r"(v) : "l"(p) : "memory");
    return v;
}
// release-scoped flag increment: bar.sync(cumulativity) + this = all CTA stores
// visible to any consumer that acquires on this flag. No membar.gl needed.
__device__ __forceinline__ void red_release_add(int* p) {
    asm volatile("red.release.gpu.global.add.s32 [%0], 1;" :: "l"(p) : "memory");
}

#define LDSM_X4(r0, r1, r2, r3, addr)                                        \
    asm volatile("ldmatrix.sync.aligned.m8n8.x4.shared.b16 {%0,%1,%2,%3}, [%4];" \
                 : "=r"(r0), "=r"(r1), "=r"(r2), "=r"(r3) : "r"(addr))
#define LDSM_X2(r0, r1, addr)                                                \
    asm volatile("ldmatrix.sync.aligned.m8n8.x2.shared.b16 {%0,%1}, [%2];"   \
                 : "=r"(r0), "=r"(r1) : "r"(addr))
#define MMA_BF16(d, a0, a1, a2, a3, b0, b1)                                  \
    asm volatile("mma.sync.aligned.m16n8k16.row.col.f32.bf16.bf16.f32 "      \
                 "{%0,%1,%2,%3}, {%4,%5,%6,%7}, {%8,%9}, {%0,%1,%2,%3};"     \
                 : "+f"(d[0]), "+f"(d[1]), "+f"(d[2]), "+f"(d[3])            \
                 : "r"(a0), "r"(a1), "r"(a2), "r"(a3), "r"(b0), "r"(b1))

// ---------------------------------------------------------------------------
// split fp32 array into bf16 hi/lo planes (memory-bound, one pass)
// ---------------------------------------------------------------------------
__global__ __launch_bounds__(256) void split_kernel(const float* __restrict__ src,
                                                    __nv_bfloat16* __restrict__ hi,
                                                    __nv_bfloat16* __restrict__ lo,
                                                    int n4) {
    int i = blockIdx.x * blockDim.x + threadIdx.x;
    if (i >= n4) return;
    float4 v = *(const float4*)(src + (size_t)i * 4);
    uint32_t p0 = pack_bf(v.x), p1 = pack_bf(v.y);
    uint32_t p2 = pack_bf(v.z), p3 = pack_bf(v.w);
    uint2 hh, ll;
    hh.x = (p0 >> 16) | (p1 & 0xffff0000u);
    hh.y = (p2 >> 16) | (p3 & 0xffff0000u);
    ll.x = (p0 & 0xffffu) | (p1 << 16);
    ll.y = (p2 & 0xffffu) | (p3 << 16);
    *(uint2*)(hi + (size_t)i * 4) = hh;
    *(uint2*)(lo + (size_t)i * 4) = ll;
}

// ---------------------------------------------------------------------------
// u[t][b][h] = sum_d x[b][t][d] * W_in[h][d] + b_in[h]   (split-bf16 HMMA)
// (unchanged — validated)
// ---------------------------------------------------------------------------
__global__ __launch_bounds__(256) void u_gemm_mma(const float* __restrict__ bin) {
    extern __shared__ char smem[];
    float* bias_sm = (float*)(smem + UBIAS);
    uint32_t sbase = (uint32_t)__cvta_generic_to_shared(smem);

    int n0 = blockIdx.x * 128;
    int m0 = blockIdx.y * 128;
    int tid = threadIdx.x;
    int w = tid >> 5, l = tid & 31;
    int wm = (w >> 2) * 64;
    int wn = (w & 3) * 32;

    if (tid < 128) bias_sm[tid] = bin[n0 + tid];

    float d[4][4][4];
#pragma unroll
    for (int mt = 0; mt < 4; mt++)
#pragma unroll
        for (int nt = 0; nt < 4; nt++)
#pragma unroll
            for (int q = 0; q < 4; q++) d[mt][nt][q] = 0.0f;

    uint32_t aRow = (uint32_t)((l & 15) * UPAD_ + ((l >> 4) & 1) * 16);
    uint32_t bRow = (uint32_t)((l & 7) * UPAD_ + ((l >> 3) & 1) * 16);

    for (int kb = 0; kb < 8; kb++) {
#pragma unroll
        for (int j = 0; j < 4; j++) {
            int idx = tid + j * 256;
            int row = idx >> 3, c = idx & 7;
            size_t asrc = (size_t)(m0 + row) * D_ + kb * 64 + c * 8;
            size_t bsrc = (size_t)(n0 + row) * D_ + kb * 64 + c * 8;
            *(uint4*)(smem + UA_H + row * UPAD_ + c * 16) = *(const uint4*)(g_xh + asrc);
            *(uint4*)(smem + UA_L + row * UPAD_ + c * 16) = *(const uint4*)(g_xl + asrc);
            *(uint4*)(smem + UB_H + row * UPAD_ + c * 16) = *(const uint4*)(g_wh + bsrc);
            *(uint4*)(smem + UB_L + row * UPAD_ + c * 16) = *(const uint4*)(g_wl + bsrc);
        }
        __syncthreads();

#pragma unroll
        for (int kk = 0; kk < 4; kk++) {
            uint32_t ka = kk * 32;
            uint32_t ah[4][4], al[4][4];
#pragma unroll
            for (int mt = 0; mt < 4; mt++) {
                uint32_t ar = sbase + (uint32_t)((wm + mt * 16) * UPAD_) + aRow + ka;
                LDSM_X4(ah[mt][0], ah[mt][1], ah[mt][2], ah[mt][3], ar + UA_H);
                LDSM_X4(al[mt][0], al[mt][1], al[mt][2], al[mt][3], ar + UA_L);
            }
#pragma unroll
            for (int nt = 0; nt < 4; nt++) {
                uint32_t br = sbase + (uint32_t)((wn + nt * 8) * UPAD_) + bRow + ka;
                uint32_t bh0, bh1, bl0, bl1;
                LDSM_X2(bh0, bh1, br + UB_H);
                LDSM_X2(bl0, bl1, br + UB_L);
#pragma unroll
                for (int mt = 0; mt < 4; mt++) {
                    MMA_BF16(d[mt][nt], ah[mt][0], ah[mt][1], ah[mt][2], ah[mt][3], bh0, bh1);
                    MMA_BF16(d[mt][nt], ah[mt][0], ah[mt][1], ah[mt][2], ah[mt][3], bl0, bl1);
                    MMA_BF16(d[mt][nt], al[mt][0], al[mt][1], al[mt][2], al[mt][3], bh0, bh1);
                }
            }
        }
        __syncthreads();
    }

#pragma unroll
    for (int mt = 0; mt < 4; mt++) {
#pragma unroll
        for (int nt = 0; nt < 4; nt++) {
            int colL = wn + nt * 8 + 2 * (l & 3);
            float b0v = bias_sm[colL], b1v = bias_sm[colL + 1];
            int r0 = m0 + wm + mt * 16 + (l >> 2);
            int r1 = r0 + 8;
            int t0 = r0 & (T_ - 1), bb0 = r0 >> 9;
            int t1 = r1 & (T_ - 1), bb1 = r1 >> 9;
            float* p0 = g_u + ((size_t)t0 * B_ + bb0) * H_ + n0 + colL;
            float* p1 = g_u + ((size_t)t1 * B_ + bb1) * H_ + n0 + colL;
            *(float2*)p0 = make_float2(d[mt][nt][0] + b0v, d[mt][nt][1] + b1v);
            *(float2*)p1 = make_float2(d[mt][nt][2] + b0v, d[mt][nt][3] + b1v);
        }
    }
}

// ---------------------------------------------------------------------------
// Persistent recurrence kernel, 512 threads/CTA, tensor-core step GEMM.
// Round 14: 3 independent MMA accumulators (hh/hl/lh passes — cuts the 48-deep
// HMMA RAW chain to 16) and release-scoped red replacing threadfence+atomicAdd
// on the producer path. Otherwise identical to round 13.
// ---------------------------------------------------------------------------
__global__ __launch_bounds__(512, 1) void rec_kernel(
    const float* __restrict__ Wst, const float* __restrict__ bst,
    const float* __restrict__ decay, const float* __restrict__ gamma,
    const float* __restrict__ beta, float* __restrict__ out) {
    extern __shared__ char smem[];
    float* red    = (float*)(smem + RED_OFF);     // [4 ks][16 b][34]
    float* red_ln = (float*)(smem + REDLN_OFF);   // [16 w][4 rows]{s,q}
    float* bcast  = (float*)(smem + BC_OFF);      // [16]x{mean,rstd} + epoch[34]
    uint32_t sbase = (uint32_t)__cvta_generic_to_shared(smem);
    uint32_t shU = sbase + SH_OFF, slU = sbase + SL_OFF;
    uint32_t whU = sbase + WH_OFF, wlU = sbase + WL_OFF;

    int g   = blockIdx.x / CPG_;
    int jc  = blockIdx.x % CPG_;
    int ch0 = jc * CHPC_;
    int b0  = g * BPG_;
    int tid = threadIdx.x;
    int w = tid >> 5, l = tid & 31;
    int ks = w >> 2, qd = w & 3;           // K-slice / N-tile + batch-quad
    int cg = w & 7, bh = w >> 3;           // output ownership (round-10 map)

    // ---- load W slice fp32 and split into bf16 hi/lo planes ----
    {
        for (int v = tid; v < CHPC_ * (H_ / 2); v += NTHR_) {
            int row = v >> 9;
            int kp  = (v & 511) * 2;
            float2 wf = *(const float2*)(Wst + (size_t)(ch0 + row) * H_ + kp);
            uint32_t p0 = pack_bf(wf.x), p1 = pack_bf(wf.y);
            uint32_t hh = (p0 >> 16) | (p1 & 0xffff0000u);
            uint32_t ll = (p0 & 0xffffu) | (p1 << 16);
            *(uint32_t*)(smem + WH_OFF + row * PSB_ + kp * 2) = hh;
            *(uint32_t*)(smem + WL_OFF + row * PSB_ + kp * 2) = ll;
        }
    }

    int myb  = bh * 8 + (l >> 2);
    int gb   = b0 + myb;
    int chl  = cg * 4 + (l & 3);
    int mych = ch0 + chl;

    float dd = 1.0f / (1.0f + expf(-decay[mych]));
    float bs = bst[mych];
    float ga = gamma[mych], be = beta[mych];
    const unsigned FULL = 0xffffffffu;

    // staging: lane l -> batch row srow_b, chunk column sc (8 uint4 each)
    int srow_b = 4 * qd + (l >> 3);
    int sc     = l & 7;

    // ldmatrix bases
    uint32_t aOff  = (uint32_t)((l & 15) * PSB_ + ((l >> 4) & 1) * 16 + 512 * ks);
    uint32_t bOff4 = (uint32_t)((8 * qd + (l & 7)) * PSB_ + ((l >> 3) & 3) * 16 + 512 * ks);

    __syncthreads();

    float snp;   // my state value (fp32, exact), register-resident
    int thr;     // flag threshold for this replay

    // ---------------- t = 0 : state is zero ----------------
    {
        float uv = __ldg(g_u + (size_t)gb * H_ + mych);
        snp = (1.0f - dd) * tanhf(uv + bs);
        __stcg(&g_stp[1][gb][mych], pack_bf(snp));
        __threadfence();
        __syncthreads();
        if (tid == 0) {
            int old = atomicAdd(&g_flag[1][g][jc], 1);
            bcast[34] = __int_as_float(old + 1);
        }
        __syncthreads();
        thr = __float_as_int(bcast[34]);
    }

    // ---------------- main loop t = 1..T-1 ----------------
    for (int t = 1; t < T_; ++t) {
        int slot  = t & 3;
        int wslot = (t + 1) & 3;
        float uv = __ldg(g_u + ((size_t)t * B_ + gb) * H_ + mych);

        // ---- per-warp poll: only this K-slice's 8 producer flags ----
        {
            const int* fp = &g_flag[t][g][8 * ks + sc];
            while (!__all_sync(FULL, ld_flag(fp) >= thr)) {}
            asm volatile("fence.acq_rel.gpu;" ::: "memory");
        }

        // ---- batched loads: 4 batch rows x 256ch K-slice, MLP=8 ----
        const uint4* srcrow = (const uint4*)&g_stp[slot][b0 + srow_b][0];
        uint4 p[8];
#pragma unroll
        for (int i = 0; i < 8; i++) p[i] = __ldcg(&srcrow[ks * 64 + sc + 8 * i]);

        // ---- unpack to hi/lo planes + LN partials (32 ch per lane) ----
        float ln_s = 0.0f, ln_q = 0.0f;
#pragma unroll
        for (int i = 0; i < 8; i++) {
            float s0 = unpack_f(p[i].x), s1 = unpack_f(p[i].y);
            float s2 = unpack_f(p[i].z), s3 = unpack_f(p[i].w);
            ln_s += s0 + s1 + s2 + s3;
            ln_q += s0 * s0 + s1 * s1 + s2 * s2 + s3 * s3;
            uint2 hh, ll;
            hh.x = (p[i].x >> 16) | (p[i].y & 0xffff0000u);
            hh.y = (p[i].z >> 16) | (p[i].w & 0xffff0000u);
            ll.x = (p[i].x & 0xffffu) | (p[i].y << 16);
            ll.y = (p[i].z & 0xffffu) | (p[i].w << 16);
            int boff = 512 * ks + sc * 8 + 64 * i;
            *(uint2*)(smem + SH_OFF + srow_b * PSB_ + boff) = hh;
            *(uint2*)(smem + SL_OFF + srow_b * PSB_ + boff) = ll;
        }
        // per-(warp,row) LN partials over 256 ch -> red_ln
        {
            float s = ln_s, q = ln_q;
#pragma unroll
            for (int dx = 1; dx <= 4; dx <<= 1) {
                s += __shfl_xor_sync(FULL, s, dx);
                q += __shfl_xor_sync(FULL, q, dx);
            }
            if (sc == 0)
                *(float2*)&red_ln[(w * 4 + (l >> 3)) * 2] = make_float2(s, q);
        }

        // ---- K-group barrier: 4 warps sharing this K-slice ----
        asm volatile("bar.sync %0, 128;" :: "r"(1 + ks) : "memory");

        // ---- MMA: 3 independent accumulators (hh/hl/lh) -> 16-deep chains ----
        float dHH[4] = {0.0f, 0.0f, 0.0f, 0.0f};
        float dHL[4] = {0.0f, 0.0f, 0.0f, 0.0f};
        float dLH[4] = {0.0f, 0.0f, 0.0f, 0.0f};
#pragma unroll
        for (int kk2 = 0; kk2 < 8; kk2++) {
            uint32_t bh0, bh1, bh2, bh3, bl0, bl1, bl2, bl3;
            LDSM_X4(bh0, bh1, bh2, bh3, whU + bOff4 + kk2 * 64);
            LDSM_X4(bl0, bl1, bl2, bl3, wlU + bOff4 + kk2 * 64);
#pragma unroll
            for (int s = 0; s < 2; s++) {
                uint32_t ah0, ah1, ah2, ah3, al0, al1, al2, al3;
                uint32_t ka = kk2 * 64 + s * 32;
                LDSM_X4(ah0, ah1, ah2, ah3, shU + aOff + ka);
                LDSM_X4(al0, al1, al2, al3, slU + aOff + ka);
                uint32_t b0f = s ? bh2 : bh0, b1f = s ? bh3 : bh1;
                uint32_t c0f = s ? bl2 : bl0, c1f = s ? bl3 : bl1;
                MMA_BF16(dHH, ah0, ah1, ah2, ah3, b0f, b1f);
                MMA_BF16(dHL, ah0, ah1, ah2, ah3, c0f, c1f);
                MMA_BF16(dLH, al0, al1, al2, al3, b0f, b1f);
            }
        }
        float d4[4];
#pragma unroll
        for (int q = 0; q < 4; q++) d4[q] = dHH[q] + (dHL[q] + dLH[q]);

        // ---- D fragments -> red[ks][b][8qd + 2(l&3)]  (stride 34: aligned) ----
        {
            int rowb = l >> 2;
            float* base = red + ks * (16 * 34) + rowb * 34 + 8 * qd + 2 * (l & 3);
            *(float2*)(base)          = make_float2(d4[0], d4[1]);
            *(float2*)(base + 8 * 34) = make_float2(d4[2], d4[3]);
        }
        __syncthreads();   // sync1: red + red_ln visible

        // LN(t-1) reduce + publish (tid<16), concurrent with everyone's gsum
        if (tid < 16) {
            float S = 0.0f, Q = 0.0f;
#pragma unroll
            for (int ksl = 0; ksl < 4; ksl++) {
                float2 v = *(const float2*)&red_ln[(16 * ksl + 4 * (tid >> 2) + (tid & 3)) * 2];
                S += v.x; Q += v.y;
            }
            float mean = S * (1.0f / H_);
            float var  = Q * (1.0f / H_) - mean * mean;
            bcast[tid * 2 + 0] = mean;
            bcast[tid * 2 + 1] = rsqrtf(var + 1e-5f);
        }

        // gsum: fixed-order sum of 4 K-partials
        float gsum = red[0 * 544 + myb * 34 + chl]
                   + red[1 * 544 + myb * 34 + chl]
                   + red[2 * 544 + myb * 34 + chl]
                   + red[3 * 544 + myb * 34 + chl];

        float dr = tanhf(uv + gsum + bs);
        float sn = dd * snp + (1.0f - dd) * dr;
        __stcg(&g_stp[wslot][gb][mych], pack_bf(sn));
        __syncthreads();   // sync2: all state stores + bcast visible (CTA-wide)
        // release-scoped flag: barrier cumulativity + release => consumers
        // that acquire on this flag see every thread's state store.
        if (tid == 0) red_release_add(&g_flag[t + 1][g][jc]);

        // y(t-1) off the critical path (after flag publish)
        {
            float mean = bcast[myb * 2 + 0], rstd = bcast[myb * 2 + 1];
            float y = (snp - mean) * rstd * ga + be;
            out[((size_t)gb * T_ + (t - 1)) * H_ + mych] = y;
        }
        snp = sn;
    }

    // ---------------- final LayerNorm for t = T-1 (state in slot 0) ----------------
    {
        const int* fp = &g_flag[T_][g][8 * ks + sc];
        while (!__all_sync(FULL, ld_flag(fp) >= thr)) {}
        asm volatile("fence.acq_rel.gpu;" ::: "memory");

        const uint4* srcrow = (const uint4*)&g_stp[0][b0 + srow_b][0];
        uint4 p[8];
#pragma unroll
        for (int i = 0; i < 8; i++) p[i] = __ldcg(&srcrow[ks * 64 + sc + 8 * i]);
        float ln_s = 0.0f, ln_q = 0.0f;
#pragma unroll
        for (int i = 0; i < 8; i++) {
            float s0 = unpack_f(p[i].x), s1 = unpack_f(p[i].y);
            float s2 = unpack_f(p[i].z), s3 = unpack_f(p[i].w);
            ln_s += s0 + s1 + s2 + s3;
            ln_q += s0 * s0 + s1 * s1 + s2 * s2 + s3 * s3;
        }
#pragma unroll
        for (int dx = 1; dx <= 4; dx <<= 1) {
            ln_s += __shfl_xor_sync(FULL, ln_s, dx);
            ln_q += __shfl_xor_sync(FULL, ln_q, dx);
        }
        if (sc == 0)
            *(float2*)&red_ln[(w * 4 + (l >> 3)) * 2] = make_float2(ln_s, ln_q);
        __syncthreads();
        if (tid < 16) {
            float S = 0.0f, Q = 0.0f;
#pragma unroll
            for (int ksl = 0; ksl < 4; ksl++) {
                float2 v = *(const float2*)&red_ln[(16 * ksl + 4 * (tid >> 2) + (tid & 3)) * 2];
                S += v.x; Q += v.y;
            }
            float mean = S * (1.0f / H_);
            float var  = Q * (1.0f / H_) - mean * mean;
            bcast[tid * 2 + 0] = mean;
            bcast[tid * 2 + 1] = rsqrtf(var + 1e-5f);
        }
        __syncthreads();
        float mean = bcast[myb * 2 + 0], rstd = bcast[myb * 2 + 1];
        float y = (snp - mean) * rstd * ga + be;
        out[((size_t)gb * T_ + (T_ - 1)) * H_ + mych] = y;
    }
}

extern "C" void kernel_launch(void* const* d_in, const int* in_sizes, int n_in,
                              void* d_out, int out_size) {
    const float* x     = (const float*)d_in[0];
    const float* Win   = (const float*)d_in[1];
    const float* bin   = (const float*)d_in[2];
    const float* Wst   = (const float*)d_in[3];
    const float* bst   = (const float*)d_in[4];
    const float* decay = (const float*)d_in[5];
    const float* gamma = (const float*)d_in[6];
    const float* beta  = (const float*)d_in[7];
    float* out = (float*)d_out;

    cudaFuncSetAttribute(rec_kernel, cudaFuncAttributeMaxDynamicSharedMemorySize,
                         SMEM_BYTES);
    cudaFuncSetAttribute(u_gemm_mma, cudaFuncAttributeMaxDynamicSharedMemorySize,
                         USMEM_BYTES);

    // split x and W_in into bf16 hi/lo planes
    {
        __nv_bfloat16 *xh, *xl, *wh, *wl;
        cudaGetSymbolAddress((void**)&xh, g_xh);
        cudaGetSymbolAddress((void**)&xl, g_xl);
        cudaGetSymbolAddress((void**)&wh, g_wh);
        cudaGetSymbolAddress((void**)&wl, g_wl);
        int nx4 = B_ * T_ * D_ / 4;
        int nw4 = H_ * D_ / 4;
        split_kernel<<<(nx4 + 255) / 256, 256>>>(x, xh, xl, nx4);
        split_kernel<<<(nw4 + 255) / 256, 256>>>(Win, wh, wl, nw4);
    }

    dim3 gg(H_ / 128, (B_ * T_) / 128);
    u_gemm_mma<<<gg, 256, USMEM_BYTES>>>(bin);
    rec_kernel<<<NCTA_, NTHR_, SMEM_BYTES>>>(Wst, bst, decay, gamma, beta, out);
}

// round 15
// speedup vs baseline: 1.1271x; 1.1271x over previous
#include <cuda_runtime.h>
#include <cuda_bf16.h>
#include <cstdint>

#define B_    64
#define T_    512
#define H_    1024
#define D_    512
#define GB_   4     // batch groups
#define CPG_  32    // CTAs (chunks) per group
#define BPG_  16    // batches per group
#define CHPC_ 32    // channels per CTA
#define NCTA_ (GB_*CPG_)
#define NTHR_ 512
#define SLOTS_ 4

#define PSB_  2064              // padded plane row stride in BYTES (1032 bf16)
#define WH_OFF 0
#define WL_OFF (32 * PSB_)               // 66048
#define SH_OFF (2 * 32 * PSB_)           // 132096
#define SL_OFF (SH_OFF + 16 * PSB_)      // 165120
#define RED_OFF (SL_OFF + 16 * PSB_)     // 198144 (dedicated, no overlay)
#define REDLN_OFF (RED_OFF + 4*16*34*4)  // 206848  (stride 34 floats = EVEN)
#define BC_OFF (REDLN_OFF + 512)         // 207360
#define SMEM_BYTES (BC_OFF + 160)

// u_gemm_mma SMEM layout: 4 planes of 128 rows x 144B + bias
#define UPAD_ 144
#define UA_H 0
#define UA_L (128 * UPAD_)
#define UB_H (2 * 128 * UPAD_)
#define UB_L (3 * 128 * UPAD_)
#define UBIAS (4 * 128 * UPAD_)
#define USMEM_BYTES (UBIAS + 512 + 32)

// scratch (static __device__ arrays: zero at module load, allocation-free)
__device__ float    g_u[(size_t)T_ * B_ * H_];       // u drive [t][b][h]
__device__ unsigned short g_sth[SLOTS_][B_][H_];     // state hi bf16 plane
__device__ unsigned short g_stl[SLOTS_][B_][H_];     // state lo bf16 plane
__device__ int      g_flag[T_ + 1][GB_][CPG_];       // monotonic chunk-ready counters
__device__ __nv_bfloat16 g_xh[(size_t)B_ * T_ * D_]; // x hi plane
__device__ __nv_bfloat16 g_xl[(size_t)B_ * T_ * D_]; // x lo plane
__device__ __nv_bfloat16 g_wh[(size_t)H_ * D_];      // W_in hi plane
__device__ __nv_bfloat16 g_wl[(size_t)H_ * D_];      // W_in lo plane

// ---- bf16 split helpers ----
__device__ __forceinline__ uint32_t pack_bf(float s) {
    __nv_bfloat16 h = __float2bfloat16(s);
    float hf = __bfloat162float(h);
    __nv_bfloat16 lo = __float2bfloat16(s - hf);
    return ((uint32_t)__bfloat16_as_ushort(h) << 16) |
           (uint32_t)__bfloat16_as_ushort(lo);
}

// ---- packed f32x2 helpers ----
__device__ __forceinline__ unsigned long long addf2(unsigned long long a,
                                                    unsigned long long b) {
    unsigned long long r;
    asm("add.rn.f32x2 %0, %1, %2;" : "=l"(r) : "l"(a), "l"(b));
    return r;
}
__device__ __forceinline__ void fmaf2(unsigned long long& acc,
                                      unsigned long long a,
                                      unsigned long long b) {
    asm("fma.rn.f32x2 %0, %1, %2, %0;" : "+l"(acc) : "l"(a), "l"(b));
}
__device__ __forceinline__ float f2_lo(unsigned long long v) {
    return __uint_as_float((unsigned)(v & 0xffffffffull));
}
__device__ __forceinline__ float f2_hi(unsigned long long v) {
    return __uint_as_float((unsigned)(v >> 32));
}
__device__ __forceinline__ unsigned long long pk64(uint32_t lo, uint32_t hi) {
    unsigned long long r;
    asm("mov.b64 %0, {%1, %2};" : "=l"(r) : "r"(lo), "r"(hi));
    return r;
}
// accumulate LN stats for 2 channels from hi-word + lo-word (bf16 pairs)
__device__ __forceinline__ void ln_acc2(uint32_t hw, uint32_t lw,
                                        unsigned long long& s2,
                                        unsigned long long& q2) {
    unsigned long long h64 = pk64(hw << 16, hw & 0xffff0000u);
    unsigned long long l64 = pk64(lw << 16, lw & 0xffff0000u);
    unsigned long long s = addf2(h64, l64);
    s2 = addf2(s2, s);
    fmaf2(q2, s, s);
}

// relaxed gpu-scope flag load (poll); pair with fence.acq_rel before data reads
__device__ __forceinline__ int ld_flag(const int* p) {
    int v;
    asm volatile("ld.relaxed.gpu.global.b32 %0, [%1];" : "=r"(v) : "l"(p) : "memory");
    return v;
}
__device__ __forceinline__ void red_release_add(int* p) {
    asm volatile("red.release.gpu.global.add.s32 [%0], 1;" :: "l"(p) : "memory");
}
__device__ __forceinline__ void st_u16_cg(unsigned short* p, unsigned short v) {
    asm volatile("st.global.cg.u16 [%0], %1;" :: "l"(p), "h"(v) : "memory");
}

#define LDSM_X4(r0, r1, r2, r3, addr)                                        \
    asm volatile("ldmatrix.sync.aligned.m8n8.x4.shared.b16 {%0,%1,%2,%3}, [%4];" \
                 : "=r"(r0), "=r"(r1), "=r"(r2), "=r"(r3) : "r"(addr))
#define LDSM_X2(r0, r1, addr)                                                \
    asm volatile("ldmatrix.sync.aligned.m8n8.x2.shared.b16 {%0,%1}, [%2];"   \
                 : "=r"(r0), "=r"(r1) : "r"(addr))
#define MMA_BF16(d, a0, a1, a2, a3, b0, b1)                                  \
    asm volatile("mma.sync.aligned.m16n8k16.row.col.f32.bf16.bf16.f32 "      \
                 "{%0,%1,%2,%3}, {%4,%5,%6,%7}, {%8,%9}, {%0,%1,%2,%3};"     \
                 : "+f"(d[0]), "+f"(d[1]), "+f"(d[2]), "+f"(d[3])            \
                 : "r"(a0), "r"(a1), "r"(a2), "r"(a3), "r"(b0), "r"(b1))

// ---------------------------------------------------------------------------
// split fp32 array into bf16 hi/lo planes (memory-bound, one pass)
// ---------------------------------------------------------------------------
__global__ __launch_bounds__(256) void split_kernel(const float* __restrict__ src,
                                                    __nv_bfloat16* __restrict__ hi,
                                                    __nv_bfloat16* __restrict__ lo,
                                                    int n4) {
    int i = blockIdx.x * blockDim.x + threadIdx.x;
    if (i >= n4) return;
    float4 v = *(const float4*)(src + (size_t)i * 4);
    uint32_t p0 = pack_bf(v.x), p1 = pack_bf(v.y);
    uint32_t p2 = pack_bf(v.z), p3 = pack_bf(v.w);
    uint2 hh, ll;
    hh.x = (p0 >> 16) | (p1 & 0xffff0000u);
    hh.y = (p2 >> 16) | (p3 & 0xffff0000u);
    ll.x = (p0 & 0xffffu) | (p1 << 16);
    ll.y = (p2 & 0xffffu) | (p3 << 16);
    *(uint2*)(hi + (size_t)i * 4) = hh;
    *(uint2*)(lo + (size_t)i * 4) = ll;
}

// ---------------------------------------------------------------------------
// u[t][b][h] = sum_d x[b][t][d] * W_in[h][d] + b_in[h]   (split-bf16 HMMA)
// Round 15: occupancy 2 (74KB smem x2 fits; hides per-K-block sync stalls)
// ---------------------------------------------------------------------------
__global__ __launch_bounds__(256, 2) void u_gemm_mma(const float* __restrict__ bin) {
    extern __shared__ char smem[];
    float* bias_sm = (float*)(smem + UBIAS);
    uint32_t sbase = (uint32_t)__cvta_generic_to_shared(smem);

    int n0 = blockIdx.x * 128;
    int m0 = blockIdx.y * 128;
    int tid = threadIdx.x;
    int w = tid >> 5, l = tid & 31;
    int wm = (w >> 2) * 64;
    int wn = (w & 3) * 32;

    if (tid < 128) bias_sm[tid] = bin[n0 + tid];

    float d[4][4][4];
#pragma unroll
    for (int mt = 0; mt < 4; mt++)
#pragma unroll
        for (int nt = 0; nt < 4; nt++)
#pragma unroll
            for (int q = 0; q < 4; q++) d[mt][nt][q] = 0.0f;

    uint32_t aRow = (uint32_t)((l & 15) * UPAD_ + ((l >> 4) & 1) * 16);
    uint32_t bRow = (uint32_t)((l & 7) * UPAD_ + ((l >> 3) & 1) * 16);

    for (int kb = 0; kb < 8; kb++) {
#pragma unroll
        for (int j = 0; j < 4; j++) {
            int idx = tid + j * 256;
            int row = idx >> 3, c = idx & 7;
            size_t asrc = (size_t)(m0 + row) * D_ + kb * 64 + c * 8;
            size_t bsrc = (size_t)(n0 + row) * D_ + kb * 64 + c * 8;
            *(uint4*)(smem + UA_H + row * UPAD_ + c * 16) = *(const uint4*)(g_xh + asrc);
            *(uint4*)(smem + UA_L + row * UPAD_ + c * 16) = *(const uint4*)(g_xl + asrc);
            *(uint4*)(smem + UB_H + row * UPAD_ + c * 16) = *(const uint4*)(g_wh + bsrc);
            *(uint4*)(smem + UB_L + row * UPAD_ + c * 16) = *(const uint4*)(g_wl + bsrc);
        }
        __syncthreads();

#pragma unroll
        for (int kk = 0; kk < 4; kk++) {
            uint32_t ka = kk * 32;
            uint32_t ah[4][4], al[4][4];
#pragma unroll
            for (int mt = 0; mt < 4; mt++) {
                uint32_t ar = sbase + (uint32_t)((wm + mt * 16) * UPAD_) + aRow + ka;
                LDSM_X4(ah[mt][0], ah[mt][1], ah[mt][2], ah[mt][3], ar + UA_H);
                LDSM_X4(al[mt][0], al[mt][1], al[mt][2], al[mt][3], ar + UA_L);
            }
#pragma unroll
            for (int nt = 0; nt < 4; nt++) {
                uint32_t br = sbase + (uint32_t)((wn + nt * 8) * UPAD_) + bRow + ka;
                uint32_t bh0, bh1, bl0, bl1;
                LDSM_X2(bh0, bh1, br + UB_H);
                LDSM_X2(bl0, bl1, br + UB_L);
#pragma unroll
                for (int mt = 0; mt < 4; mt++) {
                    MMA_BF16(d[mt][nt], ah[mt][0], ah[mt][1], ah[mt][2], ah[mt][3], bh0, bh1);
                    MMA_BF16(d[mt][nt], ah[mt][0], ah[mt][1], ah[mt][2], ah[mt][3], bl0, bl1);
                    MMA_BF16(d[mt][nt], al[mt][0], al[mt][1], al[mt][2], al[mt][3], bh0, bh1);
                }
            }
        }
        __syncthreads();
    }

#pragma unroll
    for (int mt = 0; mt < 4; mt++) {
#pragma unroll
        for (int nt = 0; nt < 4; nt++) {
            int colL = wn + nt * 8 + 2 * (l & 3);
            float b0v = bias_sm[colL], b1v = bias_sm[colL + 1];
            int r0 = m0 + wm + mt * 16 + (l >> 2);
            int r1 = r0 + 8;
            int t0 = r0 & (T_ - 1), bb0 = r0 >> 9;
            int t1 = r1 & (T_ - 1), bb1 = r1 >> 9;
            float* p0 = g_u + ((size_t)t0 * B_ + bb0) * H_ + n0 + colL;
            float* p1 = g_u + ((size_t)t1 * B_ + bb1) * H_ + n0 + colL;
            *(float2*)p0 = make_float2(d[mt][nt][0] + b0v, d[mt][nt][1] + b1v);
            *(float2*)p1 = make_float2(d[mt][nt][2] + b0v, d[mt][nt][3] + b1v);
        }
    }
}

// ---------------------------------------------------------------------------
// Persistent recurrence kernel, 512 threads/CTA, tensor-core step GEMM.
// Round 15: state kept as separate hi/lo bf16 planes -> staging is pure uint4
// copies (no swizzle), LN stats via shift/mask + packed f32x2. MMA/red/flag
// protocol identical to round 14.
// ---------------------------------------------------------------------------
__global__ __launch_bounds__(512, 1) void rec_kernel(
    const float* __restrict__ Wst, const float* __restrict__ bst,
    const float* __restrict__ decay, const float* __restrict__ gamma,
    const float* __restrict__ beta, float* __restrict__ out) {
    extern __shared__ char smem[];
    float* red    = (float*)(smem + RED_OFF);     // [4 ks][16 b][34]
    float* red_ln = (float*)(smem + REDLN_OFF);   // [16 w][4 rows]{s,q}
    float* bcast  = (float*)(smem + BC_OFF);      // [16]x{mean,rstd} + epoch[34]
    uint32_t sbase = (uint32_t)__cvta_generic_to_shared(smem);
    uint32_t shU = sbase + SH_OFF, slU = sbase + SL_OFF;
    uint32_t whU = sbase + WH_OFF, wlU = sbase + WL_OFF;

    int g   = blockIdx.x / CPG_;
    int jc  = blockIdx.x % CPG_;
    int ch0 = jc * CHPC_;
    int b0  = g * BPG_;
    int tid = threadIdx.x;
    int w = tid >> 5, l = tid & 31;
    int ks = w >> 2, qd = w & 3;           // K-slice / batch-quad
    int cg = w & 7, bh = w >> 3;           // output ownership (round-10 map)

    // ---- load W slice fp32 and split into bf16 hi/lo planes ----
    {
        for (int v = tid; v < CHPC_ * (H_ / 2); v += NTHR_) {
            int row = v >> 9;
            int kp  = (v & 511) * 2;
            float2 wf = *(const float2*)(Wst + (size_t)(ch0 + row) * H_ + kp);
            uint32_t p0 = pack_bf(wf.x), p1 = pack_bf(wf.y);
            uint32_t hh = (p0 >> 16) | (p1 & 0xffff0000u);
            uint32_t ll = (p0 & 0xffffu) | (p1 << 16);
            *(uint32_t*)(smem + WH_OFF + row * PSB_ + kp * 2) = hh;
            *(uint32_t*)(smem + WL_OFF + row * PSB_ + kp * 2) = ll;
        }
    }

    int myb  = bh * 8 + (l >> 2);
    int gb   = b0 + myb;
    int chl  = cg * 4 + (l & 3);
    int mych = ch0 + chl;

    float dd = 1.0f / (1.0f + expf(-decay[mych]));
    float bs = bst[mych];
    float ga = gamma[mych], be = beta[mych];
    const unsigned FULL = 0xffffffffu;

    // staging: lane l -> batch row srow_b, column c (4 uint4 per plane)
    int srow_b = 4 * qd + (l >> 3);
    int sc     = l & 7;

    // ldmatrix bases
    uint32_t aOff  = (uint32_t)((l & 15) * PSB_ + ((l >> 4) & 1) * 16 + 512 * ks);
    uint32_t bOff4 = (uint32_t)((8 * qd + (l & 7)) * PSB_ + ((l >> 3) & 3) * 16 + 512 * ks);

    __syncthreads();

    float snp;   // my state value (fp32, exact), register-resident
    int thr;     // flag threshold for this replay

    // ---------------- t = 0 : state is zero ----------------
    {
        float uv = __ldg(g_u + (size_t)gb * H_ + mych);
        snp = (1.0f - dd) * tanhf(uv + bs);
        __nv_bfloat16 hv = __float2bfloat16(snp);
        __nv_bfloat16 lv = __float2bfloat16(snp - __bfloat162float(hv));
        st_u16_cg(&g_sth[1][gb][mych], __bfloat16_as_ushort(hv));
        st_u16_cg(&g_stl[1][gb][mych], __bfloat16_as_ushort(lv));
        __threadfence();
        __syncthreads();
        if (tid == 0) {
            int old = atomicAdd(&g_flag[1][g][jc], 1);
            bcast[34] = __int_as_float(old + 1);
        }
        __syncthreads();
        thr = __float_as_int(bcast[34]);
    }

    // ---------------- main loop t = 1..T-1 ----------------
    for (int t = 1; t < T_; ++t) {
        int slot  = t & 3;
        int wslot = (t + 1) & 3;
        float uv = __ldg(g_u + ((size_t)t * B_ + gb) * H_ + mych);

        // ---- per-warp poll: only this K-slice's 8 producer flags ----
        {
            const int* fp = &g_flag[t][g][8 * ks + sc];
            while (!__all_sync(FULL, ld_flag(fp) >= thr)) {}
            asm volatile("fence.acq_rel.gpu;" ::: "memory");
        }

        // ---- batched loads: hi/lo plane uint4s, MLP=8 ----
        const uint4* hrow = (const uint4*)&g_sth[slot][b0 + srow_b][0];  // 128 uint4
        const uint4* lrow = (const uint4*)&g_stl[slot][b0 + srow_b][0];
        uint4 ph[4], pl[4];
#pragma unroll
        for (int j = 0; j < 4; j++) ph[j] = __ldcg(&hrow[ks * 32 + sc + 8 * j]);
#pragma unroll
        for (int j = 0; j < 4; j++) pl[j] = __ldcg(&lrow[ks * 32 + sc + 8 * j]);

        // ---- pure-copy staging + packed LN stats ----
        unsigned long long s2 = 0ull, q2 = 0ull;
#pragma unroll
        for (int j = 0; j < 4; j++) {
            int boff = 512 * ks + (sc + 8 * j) * 16;
            *(uint4*)(smem + SH_OFF + srow_b * PSB_ + boff) = ph[j];
            *(uint4*)(smem + SL_OFF + srow_b * PSB_ + boff) = pl[j];
            ln_acc2(ph[j].x, pl[j].x, s2, q2);
            ln_acc2(ph[j].y, pl[j].y, s2, q2);
            ln_acc2(ph[j].z, pl[j].z, s2, q2);
            ln_acc2(ph[j].w, pl[j].w, s2, q2);
        }
        // per-(warp,row) LN partials over 256 ch -> red_ln
        {
            float s = f2_lo(s2) + f2_hi(s2);
            float q = f2_lo(q2) + f2_hi(q2);
#pragma unroll
            for (int dx = 1; dx <= 4; dx <<= 1) {
                s += __shfl_xor_sync(FULL, s, dx);
                q += __shfl_xor_sync(FULL, q, dx);
            }
            if (sc == 0)
                *(float2*)&red_ln[(w * 4 + (l >> 3)) * 2] = make_float2(s, q);
        }

        // ---- K-group barrier: 4 warps sharing this K-slice ----
        asm volatile("bar.sync %0, 128;" :: "r"(1 + ks) : "memory");

        // ---- MMA: 3 independent accumulators (hh/hl/lh) ----
        float dHH[4] = {0.0f, 0.0f, 0.0f, 0.0f};
        float dHL[4] = {0.0f, 0.0f, 0.0f, 0.0f};
        float dLH[4] = {0.0f, 0.0f, 0.0f, 0.0f};
#pragma unroll
        for (int kk2 = 0; kk2 < 8; kk2++) {
            uint32_t bh0, bh1, bh2, bh3, bl0, bl1, bl2, bl3;
            LDSM_X4(bh0, bh1, bh2, bh3, whU + bOff4 + kk2 * 64);
            LDSM_X4(bl0, bl1, bl2, bl3, wlU + bOff4 + kk2 * 64);
#pragma unroll
            for (int s = 0; s < 2; s++) {
                uint32_t ah0, ah1, ah2, ah3, al0, al1, al2, al3;
                uint32_t ka = kk2 * 64 + s * 32;
                LDSM_X4(ah0, ah1, ah2, ah3, shU + aOff + ka);
                LDSM_X4(al0, al1, al2, al3, slU + aOff + ka);
                uint32_t b0f = s ? bh2 : bh0, b1f = s ? bh3 : bh1;
                uint32_t c0f = s ? bl2 : bl0, c1f = s ? bl3 : bl1;
                MMA_BF16(dHH, ah0, ah1, ah2, ah3, b0f, b1f);
                MMA_BF16(dHL, ah0, ah1, ah2, ah3, c0f, c1f);
                MMA_BF16(dLH, al0, al1, al2, al3, b0f, b1f);
            }
        }
        float d4[4];
#pragma unroll
        for (int q = 0; q < 4; q++) d4[q] = dHH[q] + (dHL[q] + dLH[q]);

        // ---- D fragments -> red[ks][b][8qd + 2(l&3)] ----
        {
            int rowb = l >> 2;
            float* base = red + ks * (16 * 34) + rowb * 34 + 8 * qd + 2 * (l & 3);
            *(float2*)(base)          = make_float2(d4[0], d4[1]);
            *(float2*)(base + 8 * 34) = make_float2(d4[2], d4[3]);
        }
        __syncthreads();   // sync1: red + red_ln visible

        // LN(t-1) reduce + publish (tid<16), concurrent with everyone's gsum
        if (tid < 16) {
            float S = 0.0f, Q = 0.0f;
#pragma unroll
            for (int ksl = 0; ksl < 4; ksl++) {
                float2 v = *(const float2*)&red_ln[(16 * ksl + 4 * (tid >> 2) + (tid & 3)) * 2];
                S += v.x; Q += v.y;
            }
            float mean = S * (1.0f / H_);
            float var  = Q * (1.0f / H_) - mean * mean;
            bcast[tid * 2 + 0] = mean;
            bcast[tid * 2 + 1] = rsqrtf(var + 1e-5f);
        }

        // gsum: fixed-order sum of 4 K-partials
        float gsum = red[0 * 544 + myb * 34 + chl]
                   + red[1 * 544 + myb * 34 + chl]
                   + red[2 * 544 + myb * 34 + chl]
                   + red[3 * 544 + myb * 34 + chl];

        float dr = tanhf(uv + gsum + bs);
        float sn = dd * snp + (1.0f - dd) * dr;
        {
            __nv_bfloat16 hv = __float2bfloat16(sn);
            __nv_bfloat16 lv = __float2bfloat16(sn - __bfloat162float(hv));
            st_u16_cg(&g_sth[wslot][gb][mych], __bfloat16_as_ushort(hv));
            st_u16_cg(&g_stl[wslot][gb][mych], __bfloat16_as_ushort(lv));
        }
        __syncthreads();   // sync2: all state stores + bcast visible (CTA-wide)
        if (tid == 0) red_release_add(&g_flag[t + 1][g][jc]);

        // y(t-1) off the critical path (after flag publish)
        {
            float mean = bcast[myb * 2 + 0], rstd = bcast[myb * 2 + 1];
            float y = (snp - mean) * rstd * ga + be;
            out[((size_t)gb * T_ + (t - 1)) * H_ + mych] = y;
        }
        snp = sn;
    }

    // ---------------- final LayerNorm for t = T-1 (state in slot 0) ----------------
    {
        const int* fp = &g_flag[T_][g][8 * ks + sc];
        while (!__all_sync(FULL, ld_flag(fp) >= thr)) {}
        asm volatile("fence.acq_rel.gpu;" ::: "memory");

        const uint4* hrow = (const uint4*)&g_sth[0][b0 + srow_b][0];
        const uint4* lrow = (const uint4*)&g_stl[0][b0 + srow_b][0];
        unsigned long long s2 = 0ull, q2 = 0ull;
#pragma unroll
        for (int j = 0; j < 4; j++) {
            uint4 ph = __ldcg(&hrow[ks * 32 + sc + 8 * j]);
            uint4 pl = __ldcg(&lrow[ks * 32 + sc + 8 * j]);
            ln_acc2(ph.x, pl.x, s2, q2);
            ln_acc2(ph.y, pl.y, s2, q2);
            ln_acc2(ph.z, pl.z, s2, q2);
            ln_acc2(ph.w, pl.w, s2, q2);
        }
        float ln_s = f2_lo(s2) + f2_hi(s2);
        float ln_q = f2_lo(q2) + f2_hi(q2);
#pragma unroll
        for (int dx = 1; dx <= 4; dx <<= 1) {
            ln_s += __shfl_xor_sync(FULL, ln_s, dx);
            ln_q += __shfl_xor_sync(FULL, ln_q, dx);
        }
        if (sc == 0)
            *(float2*)&red_ln[(w * 4 + (l >> 3)) * 2] = make_float2(ln_s, ln_q);
        __syncthreads();
        if (tid < 16) {
            float S = 0.0f, Q = 0.0f;
#pragma unroll
            for (int ksl = 0; ksl < 4; ksl++) {
                float2 v = *(const float2*)&red_ln[(16 * ksl + 4 * (tid >> 2) + (tid & 3)) * 2];
                S += v.x; Q += v.y;
            }
            float mean = S * (1.0f / H_);
            float var  = Q * (1.0f / H_) - mean * mean;
            bcast[tid * 2 + 0] = mean;
            bcast[tid * 2 + 1] = rsqrtf(var + 1e-5f);
        }
        __syncthreads();
        float mean = bcast[myb * 2 + 0], rstd = bcast[myb * 2 + 1];
        float y = (snp - mean) * rstd * ga + be;
        out[((size_t)gb * T_ + (T_ - 1)) * H_ + mych] = y;
    }
}

extern "C" void kernel_launch(void* const* d_in, const int* in_sizes, int n_in,
                              void* d_out, int out_size) {
    const float* x     = (const float*)d_in[0];
    const float* Win   = (const float*)d_in[1];
    const float* bin   = (const float*)d_in[2];
    const float* Wst   = (const float*)d_in[3];
    const float* bst   = (const float*)d_in[4];
    const float* decay = (const float*)d_in[5];
    const float* gamma = (const float*)d_in[6];
    const float* beta  = (const float*)d_in[7];
    float* out = (float*)d_out;

    cudaFuncSetAttribute(rec_kernel, cudaFuncAttributeMaxDynamicSharedMemorySize,
                         SMEM_BYTES);
    cudaFuncSetAttribute(u_gemm_mma, cudaFuncAttributeMaxDynamicSharedMemorySize,
                         USMEM_BYTES);

    // split x and W_in into bf16 hi/lo planes
    {
        __nv_bfloat16 *xh, *xl, *wh, *wl;
        cudaGetSymbolAddress((void**)&xh, g_xh);
        cudaGetSymbolAddress((void**)&xl, g_xl);
        cudaGetSymbolAddress((void**)&wh, g_wh);
        cudaGetSymbolAddress((void**)&wl, g_wl);
        int nx4 = B_ * T_ * D_ / 4;
        int nw4 = H_ * D_ / 4;
        split_kernel<<<(nx4 + 255) / 256, 256>>>(x, xh, xl, nx4);
        split_kernel<<<(nw4 + 255) / 256, 256>>>(Win, wh, wl, nw4);
    }

    dim3 gg(H_ / 128, (B_ * T_) / 128);
    u_gemm_mma<<<gg, 256, USMEM_BYTES>>>(bin);
    rec_kernel<<<NCTA_, NTHR_, SMEM_BYTES>>>(Wst, bst, decay, gamma, beta, out);
}

// round 16
// speedup vs baseline: 1.1805x; 1.0474x over previous
#include <cuda_runtime.h>
#include <cuda_bf16.h>
#include <cstdint>

#define B_    64
#define T_    512
#define H_    1024
#define D_    512
#define GB_   4     // batch groups
#define CPG_  32    // CTAs (chunks) per group
#define BPG_  16    // batches per group
#define CHPC_ 32    // channels per CTA
#define NCTA_ (GB_*CPG_)
#define NTHR_ 512
#define SLOTS_ 4

#define PSB_  2064              // padded plane row stride in BYTES (1032 bf16)
#define WH_OFF 0
#define WL_OFF (32 * PSB_)               // 66048
#define SH_OFF (2 * 32 * PSB_)           // 132096
#define SL_OFF (SH_OFF + 16 * PSB_)      // 165120
#define RED_OFF (SL_OFF + 16 * PSB_)     // 198144 (dedicated, no overlay)
#define REDLN_OFF (RED_OFF + 4*16*34*4)  // 206848  (stride 34 floats = EVEN)
#define BC_OFF (REDLN_OFF + 512)         // 207360
#define SMEM_BYTES (BC_OFF + 160)

// u_gemm_mma SMEM layout: 4 planes of 128 rows x 144B + bias
#define UPAD_ 144
#define UA_H 0
#define UA_L (128 * UPAD_)
#define UB_H (2 * 128 * UPAD_)
#define UB_L (3 * 128 * UPAD_)
#define UBIAS (4 * 128 * UPAD_)
#define USMEM_BYTES (UBIAS + 512 + 32)

// scratch (static __device__ arrays: zero at module load, allocation-free)
__device__ float    g_u[(size_t)T_ * B_ * H_];       // u drive [t][b][h]
__device__ unsigned short g_sth[SLOTS_][B_][H_];     // state hi bf16 plane
__device__ unsigned short g_stl[SLOTS_][B_][H_];     // state lo bf16 plane
__device__ int      g_flag[T_ + 1][GB_][CPG_];       // monotonic chunk-ready counters
__device__ __nv_bfloat16 g_xh[(size_t)B_ * T_ * D_]; // x hi plane
__device__ __nv_bfloat16 g_xl[(size_t)B_ * T_ * D_]; // x lo plane
__device__ __nv_bfloat16 g_wh[(size_t)H_ * D_];      // W_in hi plane
__device__ __nv_bfloat16 g_wl[(size_t)H_ * D_];      // W_in lo plane

// ---- bf16 split helpers ----
__device__ __forceinline__ uint32_t pack_bf(float s) {
    __nv_bfloat16 h = __float2bfloat16(s);
    float hf = __bfloat162float(h);
    __nv_bfloat16 lo = __float2bfloat16(s - hf);
    return ((uint32_t)__bfloat16_as_ushort(h) << 16) |
           (uint32_t)__bfloat16_as_ushort(lo);
}

// ---- packed f32x2 helpers ----
__device__ __forceinline__ unsigned long long addf2(unsigned long long a,
                                                    unsigned long long b) {
    unsigned long long r;
    asm("add.rn.f32x2 %0, %1, %2;" : "=l"(r) : "l"(a), "l"(b));
    return r;
}
__device__ __forceinline__ void fmaf2(unsigned long long& acc,
                                      unsigned long long a,
                                      unsigned long long b) {
    asm("fma.rn.f32x2 %0, %1, %2, %0;" : "+l"(acc) : "l"(a), "l"(b));
}
__device__ __forceinline__ float f2_lo(unsigned long long v) {
    return __uint_as_float((unsigned)(v & 0xffffffffull));
}
__device__ __forceinline__ float f2_hi(unsigned long long v) {
    return __uint_as_float((unsigned)(v >> 32));
}
__device__ __forceinline__ unsigned long long pk64(uint32_t lo, uint32_t hi) {
    unsigned long long r;
    asm("mov.b64 %0, {%1, %2};" : "=l"(r) : "r"(lo), "r"(hi));
    return r;
}
// accumulate LN stats for 2 channels from hi-word + lo-word (bf16 pairs)
__device__ __forceinline__ void ln_acc2(uint32_t hw, uint32_t lw,
                                        unsigned long long& s2,
                                        unsigned long long& q2) {
    unsigned long long h64 = pk64(hw << 16, hw & 0xffff0000u);
    unsigned long long l64 = pk64(lw << 16, lw & 0xffff0000u);
    unsigned long long s = addf2(h64, l64);
    s2 = addf2(s2, s);
    fmaf2(q2, s, s);
}

// relaxed gpu-scope flag load (poll); pair with fence.acq_rel before data reads
__device__ __forceinline__ int ld_flag(const int* p) {
    int v;
    asm volatile("ld.relaxed.gpu.global.b32 %0, [%1];" : "=r"(v) : "l"(p) : "memory");
    return v;
}
__device__ __forceinline__ void red_release_add(int* p) {
    asm volatile("red.release.gpu.global.add.s32 [%0], 1;" :: "l"(p) : "memory");
}
__device__ __forceinline__ void st_u16_cg(unsigned short* p, unsigned short v) {
    asm volatile("st.global.cg.u16 [%0], %1;" :: "l"(p), "h"(v) : "memory");
}

#define LDSM_X4(r0, r1, r2, r3, addr)                                        \
    asm volatile("ldmatrix.sync.aligned.m8n8.x4.shared.b16 {%0,%1,%2,%3}, [%4];" \
                 : "=r"(r0), "=r"(r1), "=r"(r2), "=r"(r3) : "r"(addr))
#define LDSM_X2(r0, r1, addr)                                                \
    asm volatile("ldmatrix.sync.aligned.m8n8.x2.shared.b16 {%0,%1}, [%2];"   \
                 : "=r"(r0), "=r"(r1) : "r"(addr))
#define MMA_BF16(d, a0, a1, a2, a3, b0, b1)                                  \
    asm volatile("mma.sync.aligned.m16n8k16.row.col.f32.bf16.bf16.f32 "      \
                 "{%0,%1,%2,%3}, {%4,%5,%6,%7}, {%8,%9}, {%0,%1,%2,%3};"     \
                 : "+f"(d[0]), "+f"(d[1]), "+f"(d[2]), "+f"(d[3])            \
                 : "r"(a0), "r"(a1), "r"(a2), "r"(a3), "r"(b0), "r"(b1))

// ---------------------------------------------------------------------------
// split fp32 array into bf16 hi/lo planes (memory-bound, one pass)
// ---------------------------------------------------------------------------
__global__ __launch_bounds__(256) void split_kernel(const float* __restrict__ src,
                                                    __nv_bfloat16* __restrict__ hi,
                                                    __nv_bfloat16* __restrict__ lo,
                                                    int n4) {
    int i = blockIdx.x * blockDim.x + threadIdx.x;
    if (i >= n4) return;
    float4 v = *(const float4*)(src + (size_t)i * 4);
    uint32_t p0 = pack_bf(v.x), p1 = pack_bf(v.y);
    uint32_t p2 = pack_bf(v.z), p3 = pack_bf(v.w);
    uint2 hh, ll;
    hh.x = (p0 >> 16) | (p1 & 0xffff0000u);
    hh.y = (p2 >> 16) | (p3 & 0xffff0000u);
    ll.x = (p0 & 0xffffu) | (p1 << 16);
    ll.y = (p2 & 0xffffu) | (p3 << 16);
    *(uint2*)(hi + (size_t)i * 4) = hh;
    *(uint2*)(lo + (size_t)i * 4) = ll;
}

// ---------------------------------------------------------------------------
// u[t][b][h] = sum_d x[b][t][d] * W_in[h][d] + b_in[h]   (split-bf16 HMMA)
// occupancy 2 (validated round 15)
// ---------------------------------------------------------------------------
__global__ __launch_bounds__(256, 2) void u_gemm_mma(const float* __restrict__ bin) {
    extern __shared__ char smem[];
    float* bias_sm = (float*)(smem + UBIAS);
    uint32_t sbase = (uint32_t)__cvta_generic_to_shared(smem);

    int n0 = blockIdx.x * 128;
    int m0 = blockIdx.y * 128;
    int tid = threadIdx.x;
    int w = tid >> 5, l = tid & 31;
    int wm = (w >> 2) * 64;
    int wn = (w & 3) * 32;

    if (tid < 128) bias_sm[tid] = bin[n0 + tid];

    float d[4][4][4];
#pragma unroll
    for (int mt = 0; mt < 4; mt++)
#pragma unroll
        for (int nt = 0; nt < 4; nt++)
#pragma unroll
            for (int q = 0; q < 4; q++) d[mt][nt][q] = 0.0f;

    uint32_t aRow = (uint32_t)((l & 15) * UPAD_ + ((l >> 4) & 1) * 16);
    uint32_t bRow = (uint32_t)((l & 7) * UPAD_ + ((l >> 3) & 1) * 16);

    for (int kb = 0; kb < 8; kb++) {
#pragma unroll
        for (int j = 0; j < 4; j++) {
            int idx = tid + j * 256;
            int row = idx >> 3, c = idx & 7;
            size_t asrc = (size_t)(m0 + row) * D_ + kb * 64 + c * 8;
            size_t bsrc = (size_t)(n0 + row) * D_ + kb * 64 + c * 8;
            *(uint4*)(smem + UA_H + row * UPAD_ + c * 16) = *(const uint4*)(g_xh + asrc);
            *(uint4*)(smem + UA_L + row * UPAD_ + c * 16) = *(const uint4*)(g_xl + asrc);
            *(uint4*)(smem + UB_H + row * UPAD_ + c * 16) = *(const uint4*)(g_wh + bsrc);
            *(uint4*)(smem + UB_L + row * UPAD_ + c * 16) = *(const uint4*)(g_wl + bsrc);
        }
        __syncthreads();

#pragma unroll
        for (int kk = 0; kk < 4; kk++) {
            uint32_t ka = kk * 32;
            uint32_t ah[4][4], al[4][4];
#pragma unroll
            for (int mt = 0; mt < 4; mt++) {
                uint32_t ar = sbase + (uint32_t)((wm + mt * 16) * UPAD_) + aRow + ka;
                LDSM_X4(ah[mt][0], ah[mt][1], ah[mt][2], ah[mt][3], ar + UA_H);
                LDSM_X4(al[mt][0], al[mt][1], al[mt][2], al[mt][3], ar + UA_L);
            }
#pragma unroll
            for (int nt = 0; nt < 4; nt++) {
                uint32_t br = sbase + (uint32_t)((wn + nt * 8) * UPAD_) + bRow + ka;
                uint32_t bh0, bh1, bl0, bl1;
                LDSM_X2(bh0, bh1, br + UB_H);
                LDSM_X2(bl0, bl1, br + UB_L);
#pragma unroll
                for (int mt = 0; mt < 4; mt++) {
                    MMA_BF16(d[mt][nt], ah[mt][0], ah[mt][1], ah[mt][2], ah[mt][3], bh0, bh1);
                    MMA_BF16(d[mt][nt], ah[mt][0], ah[mt][1], ah[mt][2], ah[mt][3], bl0, bl1);
                    MMA_BF16(d[mt][nt], al[mt][0], al[mt][1], al[mt][2], al[mt][3], bh0, bh1);
                }
            }
        }
        __syncthreads();
    }

#pragma unroll
    for (int mt = 0; mt < 4; mt++) {
#pragma unroll
        for (int nt = 0; nt < 4; nt++) {
            int colL = wn + nt * 8 + 2 * (l & 3);
            float b0v = bias_sm[colL], b1v = bias_sm[colL + 1];
            int r0 = m0 + wm + mt * 16 + (l >> 2);
            int r1 = r0 + 8;
            int t0 = r0 & (T_ - 1), bb0 = r0 >> 9;
            int t1 = r1 & (T_ - 1), bb1 = r1 >> 9;
            float* p0 = g_u + ((size_t)t0 * B_ + bb0) * H_ + n0 + colL;
            float* p1 = g_u + ((size_t)t1 * B_ + bb1) * H_ + n0 + colL;
            *(float2*)p0 = make_float2(d[mt][nt][0] + b0v, d[mt][nt][1] + b1v);
            *(float2*)p1 = make_float2(d[mt][nt][2] + b0v, d[mt][nt][3] + b1v);
        }
    }
}

// ---------------------------------------------------------------------------
// Persistent recurrence kernel, 512 threads/CTA, tensor-core step GEMM.
// Round 16: W_hi fragments hoisted into registers before the t-loop (32 regs,
// loop-invariant) — removes 8 LDSM_X4/warp/step (~23% of L1 bytes).
// Otherwise identical to round 15.
// ---------------------------------------------------------------------------
__global__ __launch_bounds__(512, 1) void rec_kernel(
    const float* __restrict__ Wst, const float* __restrict__ bst,
    const float* __restrict__ decay, const float* __restrict__ gamma,
    const float* __restrict__ beta, float* __restrict__ out) {
    extern __shared__ char smem[];
    float* red    = (float*)(smem + RED_OFF);     // [4 ks][16 b][34]
    float* red_ln = (float*)(smem + REDLN_OFF);   // [16 w][4 rows]{s,q}
    float* bcast  = (float*)(smem + BC_OFF);      // [16]x{mean,rstd} + epoch[34]
    uint32_t sbase = (uint32_t)__cvta_generic_to_shared(smem);
    uint32_t shU = sbase + SH_OFF, slU = sbase + SL_OFF;
    uint32_t whU = sbase + WH_OFF, wlU = sbase + WL_OFF;

    int g   = blockIdx.x / CPG_;
    int jc  = blockIdx.x % CPG_;
    int ch0 = jc * CHPC_;
    int b0  = g * BPG_;
    int tid = threadIdx.x;
    int w = tid >> 5, l = tid & 31;
    int ks = w >> 2, qd = w & 3;           // K-slice / batch-quad
    int cg = w & 7, bh = w >> 3;           // output ownership (round-10 map)

    // ---- load W slice fp32 and split into bf16 hi/lo planes ----
    {
        for (int v = tid; v < CHPC_ * (H_ / 2); v += NTHR_) {
            int row = v >> 9;
            int kp  = (v & 511) * 2;
            float2 wf = *(const float2*)(Wst + (size_t)(ch0 + row) * H_ + kp);
            uint32_t p0 = pack_bf(wf.x), p1 = pack_bf(wf.y);
            uint32_t hh = (p0 >> 16) | (p1 & 0xffff0000u);
            uint32_t ll = (p0 & 0xffffu) | (p1 << 16);
            *(uint32_t*)(smem + WH_OFF + row * PSB_ + kp * 2) = hh;
            *(uint32_t*)(smem + WL_OFF + row * PSB_ + kp * 2) = ll;
        }
    }

    int myb  = bh * 8 + (l >> 2);
    int gb   = b0 + myb;
    int chl  = cg * 4 + (l & 3);
    int mych = ch0 + chl;

    float dd = 1.0f / (1.0f + expf(-decay[mych]));
    float bs = bst[mych];
    float ga = gamma[mych], be = beta[mych];
    const unsigned FULL = 0xffffffffu;

    // staging: lane l -> batch row srow_b, column sc (4 uint4 per plane)
    int srow_b = 4 * qd + (l >> 3);
    int sc     = l & 7;

    // ldmatrix bases
    uint32_t aOff  = (uint32_t)((l & 15) * PSB_ + ((l >> 4) & 1) * 16 + 512 * ks);
    uint32_t bOff4 = (uint32_t)((8 * qd + (l & 7)) * PSB_ + ((l >> 3) & 3) * 16 + 512 * ks);

    __syncthreads();

    // ---- hoist loop-invariant W_hi fragments into registers (32 regs) ----
    uint32_t bhc[8][4];
#pragma unroll
    for (int kk2 = 0; kk2 < 8; kk2++)
        LDSM_X4(bhc[kk2][0], bhc[kk2][1], bhc[kk2][2], bhc[kk2][3],
                whU + bOff4 + kk2 * 64);

    float snp;   // my state value (fp32, exact), register-resident
    int thr;     // flag threshold for this replay

    // ---------------- t = 0 : state is zero ----------------
    {
        float uv = __ldg(g_u + (size_t)gb * H_ + mych);
        snp = (1.0f - dd) * tanhf(uv + bs);
        __nv_bfloat16 hv = __float2bfloat16(snp);
        __nv_bfloat16 lv = __float2bfloat16(snp - __bfloat162float(hv));
        st_u16_cg(&g_sth[1][gb][mych], __bfloat16_as_ushort(hv));
        st_u16_cg(&g_stl[1][gb][mych], __bfloat16_as_ushort(lv));
        __threadfence();
        __syncthreads();
        if (tid == 0) {
            int old = atomicAdd(&g_flag[1][g][jc], 1);
            bcast[34] = __int_as_float(old + 1);
        }
        __syncthreads();
        thr = __float_as_int(bcast[34]);
    }

    // ---------------- main loop t = 1..T-1 ----------------
    for (int t = 1; t < T_; ++t) {
        int slot  = t & 3;
        int wslot = (t + 1) & 3;
        float uv = __ldg(g_u + ((size_t)t * B_ + gb) * H_ + mych);

        // ---- per-warp poll: only this K-slice's 8 producer flags ----
        {
            const int* fp = &g_flag[t][g][8 * ks + sc];
            while (!__all_sync(FULL, ld_flag(fp) >= thr)) {}
            asm volatile("fence.acq_rel.gpu;" ::: "memory");
        }

        // ---- batched loads: hi/lo plane uint4s, MLP=8 ----
        const uint4* hrow = (const uint4*)&g_sth[slot][b0 + srow_b][0];  // 128 uint4
        const uint4* lrow = (const uint4*)&g_stl[slot][b0 + srow_b][0];
        uint4 ph[4], pl[4];
#pragma unroll
        for (int j = 0; j < 4; j++) ph[j] = __ldcg(&hrow[ks * 32 + sc + 8 * j]);
#pragma unroll
        for (int j = 0; j < 4; j++) pl[j] = __ldcg(&lrow[ks * 32 + sc + 8 * j]);

        // ---- pure-copy staging + packed LN stats ----
        unsigned long long s2 = 0ull, q2 = 0ull;
#pragma unroll
        for (int j = 0; j < 4; j++) {
            int boff = 512 * ks + (sc + 8 * j) * 16;
            *(uint4*)(smem + SH_OFF + srow_b * PSB_ + boff) = ph[j];
            *(uint4*)(smem + SL_OFF + srow_b * PSB_ + boff) = pl[j];
            ln_acc2(ph[j].x, pl[j].x, s2, q2);
            ln_acc2(ph[j].y, pl[j].y, s2, q2);
            ln_acc2(ph[j].z, pl[j].z, s2, q2);
            ln_acc2(ph[j].w, pl[j].w, s2, q2);
        }
        // per-(warp,row) LN partials over 256 ch -> red_ln
        {
            float s = f2_lo(s2) + f2_hi(s2);
            float q = f2_lo(q2) + f2_hi(q2);
#pragma unroll
            for (int dx = 1; dx <= 4; dx <<= 1) {
                s += __shfl_xor_sync(FULL, s, dx);
                q += __shfl_xor_sync(FULL, q, dx);
            }
            if (sc == 0)
                *(float2*)&red_ln[(w * 4 + (l >> 3)) * 2] = make_float2(s, q);
        }

        // ---- K-group barrier: 4 warps sharing this K-slice ----
        asm volatile("bar.sync %0, 128;" :: "r"(1 + ks) : "memory");

        // ---- MMA: 3 independent accumulators; W_hi frags from registers ----
        float dHH[4] = {0.0f, 0.0f, 0.0f, 0.0f};
        float dHL[4] = {0.0f, 0.0f, 0.0f, 0.0f};
        float dLH[4] = {0.0f, 0.0f, 0.0f, 0.0f};
#pragma unroll
        for (int kk2 = 0; kk2 < 8; kk2++) {
            uint32_t bl0, bl1, bl2, bl3;
            LDSM_X4(bl0, bl1, bl2, bl3, wlU + bOff4 + kk2 * 64);
#pragma unroll
            for (int s = 0; s < 2; s++) {
                uint32_t ah0, ah1, ah2, ah3, al0, al1, al2, al3;
                uint32_t ka = kk2 * 64 + s * 32;
                LDSM_X4(ah0, ah1, ah2, ah3, shU + aOff + ka);
                LDSM_X4(al0, al1, al2, al3, slU + aOff + ka);
                uint32_t b0f = s ? bhc[kk2][2] : bhc[kk2][0];
                uint32_t b1f = s ? bhc[kk2][3] : bhc[kk2][1];
                uint32_t c0f = s ? bl2 : bl0, c1f = s ? bl3 : bl1;
                MMA_BF16(dHH, ah0, ah1, ah2, ah3, b0f, b1f);
                MMA_BF16(dHL, ah0, ah1, ah2, ah3, c0f, c1f);
                MMA_BF16(dLH, al0, al1, al2, al3, b0f, b1f);
            }
        }
        float d4[4];
#pragma unroll
        for (int q = 0; q < 4; q++) d4[q] = dHH[q] + (dHL[q] + dLH[q]);

        // ---- D fragments -> red[ks][b][8qd + 2(l&3)] ----
        {
            int rowb = l >> 2;
            float* base = red + ks * (16 * 34) + rowb * 34 + 8 * qd + 2 * (l & 3);
            *(float2*)(base)          = make_float2(d4[0], d4[1]);
            *(float2*)(base + 8 * 34) = make_float2(d4[2], d4[3]);
        }
        __syncthreads();   // sync1: red + red_ln visible

        // LN(t-1) reduce + publish (tid<16), concurrent with everyone's gsum
        if (tid < 16) {
            float S = 0.0f, Q = 0.0f;
#pragma unroll
            for (int ksl = 0; ksl < 4; ksl++) {
                float2 v = *(const float2*)&red_ln[(16 * ksl + 4 * (tid >> 2) + (tid & 3)) * 2];
                S += v.x; Q += v.y;
            }
            float mean = S * (1.0f / H_);
            float var  = Q * (1.0f / H_) - mean * mean;
            bcast[tid * 2 + 0] = mean;
            bcast[tid * 2 + 1] = rsqrtf(var + 1e-5f);
        }

        // gsum: fixed-order sum of 4 K-partials
        float gsum = red[0 * 544 + myb * 34 + chl]
                   + red[1 * 544 + myb * 34 + chl]
                   + red[2 * 544 + myb * 34 + chl]
                   + red[3 * 544 + myb * 34 + chl];

        float dr = tanhf(uv + gsum + bs);
        float sn = dd * snp + (1.0f - dd) * dr;
        {
            __nv_bfloat16 hv = __float2bfloat16(sn);
            __nv_bfloat16 lv = __float2bfloat16(sn - __bfloat162float(hv));
            st_u16_cg(&g_sth[wslot][gb][mych], __bfloat16_as_ushort(hv));
            st_u16_cg(&g_stl[wslot][gb][mych], __bfloat16_as_ushort(lv));
        }
        __syncthreads();   // sync2: all state stores + bcast visible (CTA-wide)
        if (tid == 0) red_release_add(&g_flag[t + 1][g][jc]);

        // y(t-1) off the critical path (after flag publish)
        {
            float mean = bcast[myb * 2 + 0], rstd = bcast[myb * 2 + 1];
            float y = (snp - mean) * rstd * ga + be;
            out[((size_t)gb * T_ + (t - 1)) * H_ + mych] = y;
        }
        snp = sn;
    }

    // ---------------- final LayerNorm for t = T-1 (state in slot 0) ----------------
    {
        const int* fp = &g_flag[T_][g][8 * ks + sc];
        while (!__all_sync(FULL, ld_flag(fp) >= thr)) {}
        asm volatile("fence.acq_rel.gpu;" ::: "memory");

        const uint4* hrow = (const uint4*)&g_sth[0][b0 + srow_b][0];
        const uint4* lrow = (const uint4*)&g_stl[0][b0 + srow_b][0];
        unsigned long long s2 = 0ull, q2 = 0ull;
#pragma unroll
        for (int j = 0; j < 4; j++) {
            uint4 ph = __ldcg(&hrow[ks * 32 + sc + 8 * j]);
            uint4 pl = __ldcg(&lrow[ks * 32 + sc + 8 * j]);
            ln_acc2(ph.x, pl.x, s2, q2);
            ln_acc2(ph.y, pl.y, s2, q2);
            ln_acc2(ph.z, pl.z, s2, q2);
            ln_acc2(ph.w, pl.w, s2, q2);
        }
        float ln_s = f2_lo(s2) + f2_hi(s2);
        float ln_q = f2_lo(q2) + f2_hi(q2);
#pragma unroll
        for (int dx = 1; dx <= 4; dx <<= 1) {
            ln_s += __shfl_xor_sync(FULL, ln_s, dx);
            ln_q += __shfl_xor_sync(FULL, ln_q, dx);
        }
        if (sc == 0)
            *(float2*)&red_ln[(w * 4 + (l >> 3)) * 2] = make_float2(ln_s, ln_q);
        __syncthreads();
        if (tid < 16) {
            float S = 0.0f, Q = 0.0f;
#pragma unroll
            for (int ksl = 0; ksl < 4; ksl++) {
                float2 v = *(const float2*)&red_ln[(16 * ksl + 4 * (tid >> 2) + (tid & 3)) * 2];
                S += v.x; Q += v.y;
            }
            float mean = S * (1.0f / H_);
            float var  = Q * (1.0f / H_) - mean * mean;
            bcast[tid * 2 + 0] = mean;
            bcast[tid * 2 + 1] = rsqrtf(var + 1e-5f);
        }
        __syncthreads();
        float mean = bcast[myb * 2 + 0], rstd = bcast[myb * 2 + 1];
        float y = (snp - mean) * rstd * ga + be;
        out[((size_t)gb * T_ + (T_ - 1)) * H_ + mych] = y;
    }
}

extern "C" void kernel_launch(void* const* d_in, const int* in_sizes, int n_in,
                              void* d_out, int out_size) {
    const float* x     = (const float*)d_in[0];
    const float* Win   = (const float*)d_in[1];
    const float* bin   = (const float*)d_in[2];
    const float* Wst   = (const float*)d_in[3];
    const float* bst   = (const float*)d_in[4];
    const float* decay = (const float*)d_in[5];
    const float* gamma = (const float*)d_in[6];
    const float* beta  = (const float*)d_in[7];
    float* out = (float*)d_out;

    cudaFuncSetAttribute(rec_kernel, cudaFuncAttributeMaxDynamicSharedMemorySize,
                         SMEM_BYTES);
    cudaFuncSetAttribute(u_gemm_mma, cudaFuncAttributeMaxDynamicSharedMemorySize,
                         USMEM_BYTES);

    // split x and W_in into bf16 hi/lo planes
    {
        __nv_bfloat16 *xh, *xl, *wh, *wl;
        cudaGetSymbolAddress((void**)&xh, g_xh);
        cudaGetSymbolAddress((void**)&xl, g_xl);
        cudaGetSymbolAddress((void**)&wh, g_wh);
        cudaGetSymbolAddress((void**)&wl, g_wl);
        int nx4 = B_ * T_ * D_ / 4;
        int nw4 = H_ * D_ / 4;
        split_kernel<<<(nx4 + 255) / 256, 256>>>(x, xh, xl, nx4);
        split_kernel<<<(nw4 + 255) / 256, 256>>>(Win, wh, wl, nw4);
    }

    dim3 gg(H_ / 128, (B_ * T_) / 128);
    u_gemm_mma<<<gg, 256, USMEM_BYTES>>>(bin);
    rec_kernel<<<NCTA_, NTHR_, SMEM_BYTES>>>(Wst, bst, decay, gamma, beta, out);
}